// round 1
// baseline (speedup 1.0000x reference)
#include <cuda_runtime.h>
#include <cuda_bf16.h>
#include <math.h>

#define BATCH 512
#define SEQ 256
#define EMBED 384
#define HEAD 64

// Scratch for projected Q, K, V (each 512*256*64 floats = 33.5 MB)
__device__ float g_Q[BATCH * SEQ * HEAD];
__device__ float g_K[BATCH * SEQ * HEAD];
__device__ float g_V[BATCH * SEQ * HEAD];

// ---------------------------------------------------------------------------
// Kernel 1: fused projection GEMM.  Computes Q, K, V = X @ Wq/Wk/Wv.
// X is [131072, 384]; each block does a 64-row tile, full 64-col output,
// k-chunks of 32 through shared memory. 4x4 register blocking per thread,
// 3 output matrices => 48 accumulators.
// ---------------------------------------------------------------------------
__global__ __launch_bounds__(256, 1)
void proj_kernel(const float* __restrict__ X,
                 const float* __restrict__ Wk,
                 const float* __restrict__ Wq,
                 const float* __restrict__ Wv)
{
    __shared__ float Xs[64][32];
    __shared__ float Wks[32][64];
    __shared__ float Wqs[32][64];
    __shared__ float Wvs[32][64];

    const int tid = threadIdx.x;
    const int ty = tid >> 4;   // 0..15 -> owns rows ty*4 .. ty*4+3
    const int tx = tid & 15;   // 0..15 -> owns cols tx*4 .. tx*4+3
    const int r0 = blockIdx.x * 64;

    float accK[16], accQ[16], accV[16];
#pragma unroll
    for (int i = 0; i < 16; i++) { accK[i] = 0.f; accQ[i] = 0.f; accV[i] = 0.f; }

    for (int kk = 0; kk < EMBED; kk += 32) {
        // Load X tile: 64x32 = 2048 floats, 8 per thread (two float4)
        {
            int base = tid * 8;
            int row = base >> 5;
            int col = base & 31;
            const float* src = X + (size_t)(r0 + row) * EMBED + kk + col;
            float4 v0 = *(const float4*)(src);
            float4 v1 = *(const float4*)(src + 4);
            *(float4*)&Xs[row][col]     = v0;
            *(float4*)&Xs[row][col + 4] = v1;
        }
        // Load W tiles: 32x64 = 2048 floats each
        {
            int base = tid * 8;
            int wr = base >> 6;
            int wc = base & 63;
            const float* sk = Wk + (size_t)(kk + wr) * HEAD + wc;
            const float* sq = Wq + (size_t)(kk + wr) * HEAD + wc;
            const float* sv = Wv + (size_t)(kk + wr) * HEAD + wc;
            *(float4*)&Wks[wr][wc]     = *(const float4*)(sk);
            *(float4*)&Wks[wr][wc + 4] = *(const float4*)(sk + 4);
            *(float4*)&Wqs[wr][wc]     = *(const float4*)(sq);
            *(float4*)&Wqs[wr][wc + 4] = *(const float4*)(sq + 4);
            *(float4*)&Wvs[wr][wc]     = *(const float4*)(sv);
            *(float4*)&Wvs[wr][wc + 4] = *(const float4*)(sv + 4);
        }
        __syncthreads();

#pragma unroll 4
        for (int k = 0; k < 32; k++) {
            float a0 = Xs[ty * 4 + 0][k];
            float a1 = Xs[ty * 4 + 1][k];
            float a2 = Xs[ty * 4 + 2][k];
            float a3 = Xs[ty * 4 + 3][k];
            float4 bk = *(const float4*)&Wks[k][tx * 4];
            float4 bq = *(const float4*)&Wqs[k][tx * 4];
            float4 bv = *(const float4*)&Wvs[k][tx * 4];

            accK[0]  = fmaf(a0, bk.x, accK[0]);  accK[1]  = fmaf(a0, bk.y, accK[1]);
            accK[2]  = fmaf(a0, bk.z, accK[2]);  accK[3]  = fmaf(a0, bk.w, accK[3]);
            accK[4]  = fmaf(a1, bk.x, accK[4]);  accK[5]  = fmaf(a1, bk.y, accK[5]);
            accK[6]  = fmaf(a1, bk.z, accK[6]);  accK[7]  = fmaf(a1, bk.w, accK[7]);
            accK[8]  = fmaf(a2, bk.x, accK[8]);  accK[9]  = fmaf(a2, bk.y, accK[9]);
            accK[10] = fmaf(a2, bk.z, accK[10]); accK[11] = fmaf(a2, bk.w, accK[11]);
            accK[12] = fmaf(a3, bk.x, accK[12]); accK[13] = fmaf(a3, bk.y, accK[13]);
            accK[14] = fmaf(a3, bk.z, accK[14]); accK[15] = fmaf(a3, bk.w, accK[15]);

            accQ[0]  = fmaf(a0, bq.x, accQ[0]);  accQ[1]  = fmaf(a0, bq.y, accQ[1]);
            accQ[2]  = fmaf(a0, bq.z, accQ[2]);  accQ[3]  = fmaf(a0, bq.w, accQ[3]);
            accQ[4]  = fmaf(a1, bq.x, accQ[4]);  accQ[5]  = fmaf(a1, bq.y, accQ[5]);
            accQ[6]  = fmaf(a1, bq.z, accQ[6]);  accQ[7]  = fmaf(a1, bq.w, accQ[7]);
            accQ[8]  = fmaf(a2, bq.x, accQ[8]);  accQ[9]  = fmaf(a2, bq.y, accQ[9]);
            accQ[10] = fmaf(a2, bq.z, accQ[10]); accQ[11] = fmaf(a2, bq.w, accQ[11]);
            accQ[12] = fmaf(a3, bq.x, accQ[12]); accQ[13] = fmaf(a3, bq.y, accQ[13]);
            accQ[14] = fmaf(a3, bq.z, accQ[14]); accQ[15] = fmaf(a3, bq.w, accQ[15]);

            accV[0]  = fmaf(a0, bv.x, accV[0]);  accV[1]  = fmaf(a0, bv.y, accV[1]);
            accV[2]  = fmaf(a0, bv.z, accV[2]);  accV[3]  = fmaf(a0, bv.w, accV[3]);
            accV[4]  = fmaf(a1, bv.x, accV[4]);  accV[5]  = fmaf(a1, bv.y, accV[5]);
            accV[6]  = fmaf(a1, bv.z, accV[6]);  accV[7]  = fmaf(a1, bv.w, accV[7]);
            accV[8]  = fmaf(a2, bv.x, accV[8]);  accV[9]  = fmaf(a2, bv.y, accV[9]);
            accV[10] = fmaf(a2, bv.z, accV[10]); accV[11] = fmaf(a2, bv.w, accV[11]);
            accV[12] = fmaf(a3, bv.x, accV[12]); accV[13] = fmaf(a3, bv.y, accV[13]);
            accV[14] = fmaf(a3, bv.z, accV[14]); accV[15] = fmaf(a3, bv.w, accV[15]);
        }
        __syncthreads();
    }

    // Epilogue: write 4x4 per matrix
#pragma unroll
    for (int i = 0; i < 4; i++) {
        size_t row = (size_t)(r0 + ty * 4 + i);
        size_t off = row * HEAD + tx * 4;
        float4 vk = make_float4(accK[i*4+0], accK[i*4+1], accK[i*4+2], accK[i*4+3]);
        float4 vq = make_float4(accQ[i*4+0], accQ[i*4+1], accQ[i*4+2], accQ[i*4+3]);
        float4 vv = make_float4(accV[i*4+0], accV[i*4+1], accV[i*4+2], accV[i*4+3]);
        *(float4*)&g_K[off] = vk;
        *(float4*)&g_Q[off] = vq;
        *(float4*)&g_V[off] = vv;
    }
}

// ---------------------------------------------------------------------------
// Kernel 2: causal attention per batch. One block per batch; K,V for the
// whole batch live in shared memory (padded rows). One warp per q-row,
// rows strided across warps for causal load balance.
// ---------------------------------------------------------------------------
#define PAD 68   // 68 floats = 272 bytes: 16B-aligned rows, conflict-free f4 reads

__global__ __launch_bounds__(256, 1)
void attn_kernel(float* __restrict__ out)
{
    extern __shared__ float smem[];
    float* Ks   = smem;                 // [256][PAD]
    float* Vs   = Ks + SEQ * PAD;       // [256][PAD]
    float* qbuf = Vs + SEQ * PAD;       // [8][64]
    float* sc   = qbuf + 8 * 64;        // [8][256]

    const int b    = blockIdx.x;
    const int tid  = threadIdx.x;
    const int lane = tid & 31;
    const int warp = tid >> 5;

    const size_t base = (size_t)b * SEQ * HEAD;

    // Stage K and V for this batch into smem (coalesced)
    for (int i = tid; i < SEQ * HEAD; i += 256) {
        int s = i >> 6;      // /64
        int d = i & 63;
        Ks[s * PAD + d] = g_K[base + i];
        Vs[s * PAD + d] = g_V[base + i];
    }
    __syncthreads();

    float* qw = qbuf + warp * 64;
    float* sw = sc + warp * SEQ;

    for (int r = warp; r < SEQ; r += 8) {
        // Load this row's q into per-warp smem buffer
        const float* qrow = g_Q + base + (size_t)r * HEAD;
        qw[lane]      = qrow[lane];
        qw[lane + 32] = qrow[lane + 32];
        __syncwarp();

        const int nk  = r + 1;           // causal: keys 0..r
        const int nkb = (nk + 31) >> 5;

        // Scores (scaled), tracking running max
        float m = -1e30f;
        for (int kb = 0; kb < nkb; kb++) {
            int k = kb * 32 + lane;
            float s = -1e30f;
            if (k < nk) {
                const float* kr = &Ks[k * PAD];
                float acc = 0.f;
#pragma unroll
                for (int d = 0; d < HEAD; d += 4) {
                    float4 q4 = *(const float4*)&qw[d];
                    float4 k4 = *(const float4*)&kr[d];
                    acc = fmaf(q4.x, k4.x, acc);
                    acc = fmaf(q4.y, k4.y, acc);
                    acc = fmaf(q4.z, k4.z, acc);
                    acc = fmaf(q4.w, k4.w, acc);
                }
                s = acc * 0.125f;   // 1/sqrt(64)
            }
            sw[kb * 32 + lane] = s;
            m = fmaxf(m, s);
        }
#pragma unroll
        for (int off = 16; off; off >>= 1)
            m = fmaxf(m, __shfl_xor_sync(0xFFFFFFFFu, m, off));

        // exp + sum
        float l = 0.f;
        for (int kb = 0; kb < nkb; kb++) {
            int k = kb * 32 + lane;
            float p = 0.f;
            if (k < nk) p = __expf(sw[k] - m);
            sw[k] = p;
            l += p;
        }
#pragma unroll
        for (int off = 16; off; off >>= 1)
            l += __shfl_xor_sync(0xFFFFFFFFu, l, off);
        float inv = 1.f / l;

        // PV: each lane owns 2 head dims
        const int d0 = lane * 2;
        float o0 = 0.f, o1 = 0.f;
        for (int k = 0; k < nk; k++) {
            float p = sw[k];
            float2 v2 = *(const float2*)&Vs[k * PAD + d0];
            o0 = fmaf(p, v2.x, o0);
            o1 = fmaf(p, v2.y, o1);
        }
        float2 res = make_float2(o0 * inv, o1 * inv);
        *(float2*)&out[base + (size_t)r * HEAD + d0] = res;
        __syncwarp();
    }
}

// ---------------------------------------------------------------------------
extern "C" void kernel_launch(void* const* d_in, const int* in_sizes, int n_in,
                              void* d_out, int out_size)
{
    const float* X  = (const float*)d_in[0];
    const float* Wk = (const float*)d_in[1];
    const float* Wq = (const float*)d_in[2];
    const float* Wv = (const float*)d_in[3];
    float* out = (float*)d_out;

    // Kernel 1: projections. 131072 rows / 64 per block = 2048 blocks.
    proj_kernel<<<(BATCH * SEQ) / 64, 256>>>(X, Wk, Wq, Wv);

    // Kernel 2: attention. 512 blocks, dynamic smem for K/V/q/scores.
    const int smem_bytes = (2 * SEQ * PAD + 8 * 64 + 8 * SEQ) * (int)sizeof(float);
    static bool attr_set = false;
    if (!attr_set) {
        cudaFuncSetAttribute(attn_kernel,
                             cudaFuncAttributeMaxDynamicSharedMemorySize,
                             smem_bytes);
        attr_set = true;
    }
    attn_kernel<<<BATCH, 256, smem_bytes>>>(out);
}

// round 2
// speedup vs baseline: 2.4482x; 2.4482x over previous
#include <cuda_runtime.h>
#include <cuda_bf16.h>
#include <math.h>

#define BATCH 512
#define SEQ 256
#define EMBED 384
#define HEAD 64

// Scratch for projected Q, K, V (each 512*256*64 floats = 33.5 MB)
__device__ float g_Q[BATCH * SEQ * HEAD];
__device__ float g_K[BATCH * SEQ * HEAD];
__device__ float g_V[BATCH * SEQ * HEAD];

// ---------------------------------------------------------------------------
// tf32 helpers
// ---------------------------------------------------------------------------
__device__ __forceinline__ unsigned f2tf(float x) {
    unsigned r;
    asm("cvt.rna.tf32.f32 %0, %1;" : "=r"(r) : "f"(x));
    return r;
}

__device__ __forceinline__ void mma_tf32(float* d, const unsigned* a,
                                         unsigned b0, unsigned b1) {
    asm volatile(
        "mma.sync.aligned.m16n8k8.row.col.f32.tf32.tf32.f32 "
        "{%0,%1,%2,%3}, {%4,%5,%6,%7}, {%8,%9}, {%0,%1,%2,%3};\n"
        : "+f"(d[0]), "+f"(d[1]), "+f"(d[2]), "+f"(d[3])
        : "r"(a[0]), "r"(a[1]), "r"(a[2]), "r"(a[3]), "r"(b0), "r"(b1));
}

// ---------------------------------------------------------------------------
// Kernel 1: fused projection as ONE tf32 GEMM.
// C[131072 x 192] = X[131072 x 384] @ [Wk | Wq | Wv] (384 x 192)
// Block: 256 thr (8 warps), tile M=64, N=192, k-chunk 32.
// Warp grid 4(m) x 2(n); warp tile 16 x 96 = 12 n-fragments of m16n8k8.
// ---------------------------------------------------------------------------
#define XPAD 36   // 64x36 floats; bank = (row*4 + col) % 32 -> conflict-free frags
#define WPAD 200  // 32x200 floats; bank = (row*8 + g) % 32 -> conflict-free frags

__global__ __launch_bounds__(256, 1)
void proj_kernel(const float* __restrict__ X,
                 const float* __restrict__ Wk,
                 const float* __restrict__ Wq,
                 const float* __restrict__ Wv)
{
    __shared__ float Xs[64][XPAD];
    __shared__ float Ws[32][WPAD];

    const int tid  = threadIdx.x;
    const int lane = tid & 31;
    const int warp = tid >> 5;
    const int g = lane >> 2;   // group id  (0..7)
    const int t = lane & 3;    // tid in group (0..3)
    const int wm = warp & 3;   // warp m index (rows wm*16..+15)
    const int wn = warp >> 2;  // warp n index (cols wn*96..+95)
    const int r0 = blockIdx.x * 64;

    float acc[12][4];
#pragma unroll
    for (int f = 0; f < 12; f++)
#pragma unroll
        for (int j = 0; j < 4; j++) acc[f][j] = 0.f;

    for (int kk = 0; kk < EMBED; kk += 32) {
        // Load X tile 64x32: 512 float4, 2 per thread
#pragma unroll
        for (int i = 0; i < 2; i++) {
            int idx = tid * 2 + i;          // float4 index
            int row = idx >> 3;
            int col = (idx & 7) * 4;
            *(float4*)&Xs[row][col] =
                *(const float4*)(X + (size_t)(r0 + row) * EMBED + kk + col);
        }
        // Load W tile 32x192 (concat K|Q|V): 1536 float4, 6 per thread
#pragma unroll
        for (int i = 0; i < 6; i++) {
            int idx = tid + i * 256;
            int row = idx / 48;
            int col = (idx % 48) * 4;
            const float* src;
            if (col < 64)       src = Wk + (size_t)(kk + row) * HEAD + col;
            else if (col < 128) src = Wq + (size_t)(kk + row) * HEAD + (col - 64);
            else                src = Wv + (size_t)(kk + row) * HEAD + (col - 128);
            *(float4*)&Ws[row][col] = *(const float4*)src;
        }
        __syncthreads();

#pragma unroll
        for (int ks = 0; ks < 4; ks++) {
            const int kb = ks * 8;
            unsigned a[4];
            a[0] = f2tf(Xs[wm * 16 + g][kb + t]);
            a[1] = f2tf(Xs[wm * 16 + g + 8][kb + t]);
            a[2] = f2tf(Xs[wm * 16 + g][kb + t + 4]);
            a[3] = f2tf(Xs[wm * 16 + g + 8][kb + t + 4]);
#pragma unroll
            for (int f = 0; f < 12; f++) {
                int col = wn * 96 + f * 8 + g;
                unsigned b0 = f2tf(Ws[kb + t][col]);
                unsigned b1 = f2tf(Ws[kb + t + 4][col]);
                mma_tf32(acc[f], a, b0, b1);
            }
        }
        __syncthreads();
    }

    // Epilogue: route columns to K / Q / V
#pragma unroll
    for (int f = 0; f < 12; f++) {
        int n = wn * 96 + f * 8 + 2 * t;
        float* dst;
        int nn;
        if (n < 64)       { dst = g_K; nn = n; }
        else if (n < 128) { dst = g_Q; nn = n - 64; }
        else              { dst = g_V; nn = n - 128; }
        size_t row = (size_t)(r0 + wm * 16 + g);
        *(float2*)&dst[row * HEAD + nn]       = make_float2(acc[f][0], acc[f][1]);
        *(float2*)&dst[(row + 8) * HEAD + nn] = make_float2(acc[f][2], acc[f][3]);
    }
}

// ---------------------------------------------------------------------------
// Kernel 2: causal attention, tf32 tensor cores, flash-style online softmax.
// One block per batch (512 blocks, 256 thr = 8 warps).
// Each warp handles q-tiles {w, 15-w} (16 rows each) -> balanced causal work.
// KV chunked by 32 columns.
// ---------------------------------------------------------------------------
#define KVPAD 68  // bank = (row_or_col*4 + x) % 32 -> conflict-free frag loads
#define QPAD  68
#define PPAD  36

__global__ __launch_bounds__(256, 1)
void attn_kernel(float* __restrict__ out)
{
    extern __shared__ float sm[];
    float* Ks = sm;                       // [256][KVPAD]
    float* Vs = Ks + SEQ * KVPAD;         // [256][KVPAD]
    float* Qs = Vs + SEQ * KVPAD;         // [8][16][QPAD]
    float* Pb = Qs + 8 * 16 * QPAD;       // [8][16][PPAD]

    const int b    = blockIdx.x;
    const int tid  = threadIdx.x;
    const int lane = tid & 31;
    const int warp = tid >> 5;
    const int g = lane >> 2;
    const int t = lane & 3;
    const size_t base = (size_t)b * SEQ * HEAD;

    // Stage K, V for this batch (coalesced)
    for (int i = tid; i < SEQ * HEAD; i += 256) {
        int s = i >> 6;
        int d = i & 63;
        Ks[s * KVPAD + d] = g_K[base + i];
        Vs[s * KVPAD + d] = g_V[base + i];
    }
    __syncthreads();

    float* Qw = Qs + warp * 16 * QPAD;
    float* Pw = Pb + warp * 16 * PPAD;

#pragma unroll
    for (int pass = 0; pass < 2; pass++) {
        const int qt = pass ? (15 - warp) : warp;
        const int qr0 = qt * 16;

        // Stage this warp's 16x64 Q tile (coalesced float4)
#pragma unroll
        for (int i = 0; i < 8; i++) {
            int idx = lane + i * 32;      // float4 index, 256 total
            int row = idx >> 4;
            int c4  = (idx & 15) * 4;
            *(float4*)&Qw[row * QPAD + c4] =
                *(const float4*)&g_Q[base + (size_t)(qr0 + row) * HEAD + c4];
        }
        __syncwarp();

        // Q fragments for 8 k-steps (k = head dim 64)
        unsigned qf[8][4];
#pragma unroll
        for (int ks = 0; ks < 8; ks++) {
            int kb = ks * 8;
            qf[ks][0] = f2tf(Qw[g * QPAD + kb + t]);
            qf[ks][1] = f2tf(Qw[(g + 8) * QPAD + kb + t]);
            qf[ks][2] = f2tf(Qw[g * QPAD + kb + t + 4]);
            qf[ks][3] = f2tf(Qw[(g + 8) * QPAD + kb + t + 4]);
        }

        float of[8][4];
#pragma unroll
        for (int f = 0; f < 8; f++)
#pragma unroll
            for (int j = 0; j < 4; j++) of[f][j] = 0.f;

        float m0 = -1e30f, m1 = -1e30f, l0 = 0.f, l1 = 0.f;
        const int rg  = qr0 + g;
        const int rg8 = rg + 8;
        const int jmax = (qr0 + 15) >> 5;

        for (int j = 0; j <= jmax; j++) {
            // ---- scores S = Q @ K^T for kv chunk [j*32, j*32+31] ----
            float s[4][4];
#pragma unroll
            for (int nf = 0; nf < 4; nf++)
#pragma unroll
                for (int e = 0; e < 4; e++) s[nf][e] = 0.f;

#pragma unroll
            for (int ks = 0; ks < 8; ks++) {
                int kb = ks * 8;
#pragma unroll
                for (int nf = 0; nf < 4; nf++) {
                    int col = j * 32 + nf * 8 + g;
                    unsigned b0 = f2tf(Ks[col * KVPAD + kb + t]);
                    unsigned b1 = f2tf(Ks[col * KVPAD + kb + t + 4]);
                    mma_tf32(s[nf], qf[ks], b0, b1);
                }
            }

            // scale + causal mask (only the last kv tile can cross the diag)
#pragma unroll
            for (int nf = 0; nf < 4; nf++) {
                int c0 = j * 32 + nf * 8 + 2 * t;
                s[nf][0] *= 0.125f; s[nf][1] *= 0.125f;
                s[nf][2] *= 0.125f; s[nf][3] *= 0.125f;
                if (j == jmax) {
                    if (c0 > rg)      s[nf][0] = -1e30f;
                    if (c0 + 1 > rg)  s[nf][1] = -1e30f;
                    if (c0 > rg8)     s[nf][2] = -1e30f;
                    if (c0 + 1 > rg8) s[nf][3] = -1e30f;
                }
            }

            // ---- online softmax: row maxima (rows g and g+8) ----
            float nm0 = m0, nm1 = m1;
#pragma unroll
            for (int nf = 0; nf < 4; nf++) {
                nm0 = fmaxf(nm0, fmaxf(s[nf][0], s[nf][1]));
                nm1 = fmaxf(nm1, fmaxf(s[nf][2], s[nf][3]));
            }
            nm0 = fmaxf(nm0, __shfl_xor_sync(0xFFFFFFFFu, nm0, 1));
            nm0 = fmaxf(nm0, __shfl_xor_sync(0xFFFFFFFFu, nm0, 2));
            nm1 = fmaxf(nm1, __shfl_xor_sync(0xFFFFFFFFu, nm1, 1));
            nm1 = fmaxf(nm1, __shfl_xor_sync(0xFFFFFFFFu, nm1, 2));

            float al0 = __expf(m0 - nm0);
            float al1 = __expf(m1 - nm1);

            float ps0 = 0.f, ps1 = 0.f;
#pragma unroll
            for (int nf = 0; nf < 4; nf++) {
                float p0 = __expf(s[nf][0] - nm0);
                float p1 = __expf(s[nf][1] - nm0);
                float p2 = __expf(s[nf][2] - nm1);
                float p3 = __expf(s[nf][3] - nm1);
                ps0 += p0 + p1;
                ps1 += p2 + p3;
                int cl = nf * 8 + 2 * t;
                *(float2*)&Pw[g * PPAD + cl]       = make_float2(p0, p1);
                *(float2*)&Pw[(g + 8) * PPAD + cl] = make_float2(p2, p3);
            }
            ps0 += __shfl_xor_sync(0xFFFFFFFFu, ps0, 1);
            ps0 += __shfl_xor_sync(0xFFFFFFFFu, ps0, 2);
            ps1 += __shfl_xor_sync(0xFFFFFFFFu, ps1, 1);
            ps1 += __shfl_xor_sync(0xFFFFFFFFu, ps1, 2);

            l0 = l0 * al0 + ps0;
            l1 = l1 * al1 + ps1;
            m0 = nm0; m1 = nm1;

            // rescale running O
#pragma unroll
            for (int f = 0; f < 8; f++) {
                of[f][0] *= al0; of[f][1] *= al0;
                of[f][2] *= al1; of[f][3] *= al1;
            }
            __syncwarp();   // P writes visible to whole warp

            // ---- O += P @ V  (k = 32 kv positions -> 4 k-steps) ----
#pragma unroll
            for (int ks = 0; ks < 4; ks++) {
                int kb = ks * 8;
                unsigned pa[4];
                pa[0] = f2tf(Pw[g * PPAD + kb + t]);
                pa[1] = f2tf(Pw[(g + 8) * PPAD + kb + t]);
                pa[2] = f2tf(Pw[g * PPAD + kb + t + 4]);
                pa[3] = f2tf(Pw[(g + 8) * PPAD + kb + t + 4]);
                int vr = j * 32 + kb;
#pragma unroll
                for (int nf = 0; nf < 8; nf++) {
                    int col = nf * 8 + g;
                    unsigned b0 = f2tf(Vs[(vr + t) * KVPAD + col]);
                    unsigned b1 = f2tf(Vs[(vr + t + 4) * KVPAD + col]);
                    mma_tf32(of[nf], pa, b0, b1);
                }
            }
            __syncwarp();   // done reading P before next tile overwrites
        }

        // Epilogue: normalize and store
        float inv0 = 1.f / l0;
        float inv1 = 1.f / l1;
#pragma unroll
        for (int nf = 0; nf < 8; nf++) {
            int col = nf * 8 + 2 * t;
            size_t row = (size_t)(qr0 + g);
            *(float2*)&out[base + row * HEAD + col] =
                make_float2(of[nf][0] * inv0, of[nf][1] * inv0);
            *(float2*)&out[base + (row + 8) * HEAD + col] =
                make_float2(of[nf][2] * inv1, of[nf][3] * inv1);
        }
    }
}

// ---------------------------------------------------------------------------
extern "C" void kernel_launch(void* const* d_in, const int* in_sizes, int n_in,
                              void* d_out, int out_size)
{
    const float* X  = (const float*)d_in[0];
    const float* Wk = (const float*)d_in[1];
    const float* Wq = (const float*)d_in[2];
    const float* Wv = (const float*)d_in[3];
    float* out = (float*)d_out;

    proj_kernel<<<(BATCH * SEQ) / 64, 256>>>(X, Wk, Wq, Wv);

    const int smem_bytes =
        (2 * SEQ * KVPAD + 8 * 16 * QPAD + 8 * 16 * PPAD) * (int)sizeof(float);
    static bool attr_set = false;
    if (!attr_set) {
        cudaFuncSetAttribute(attn_kernel,
                             cudaFuncAttributeMaxDynamicSharedMemorySize,
                             smem_bytes);
        attr_set = true;
    }
    attn_kernel<<<BATCH, 256, smem_bytes>>>(out);
}